// round 13
// baseline (speedup 1.0000x reference)
#include <cuda_runtime.h>
#include <math.h>

// 17 accumulators per batch:
// [0]=sum|w|, [1]=sum w, [2..4]=sum w*X, [5..7]=sum w*Y, [8..16]=sum w*Y_i*X_j
#define NACC 17
#define MAXB 64
#define NBLK 46    // 46 x 16 = 736 blocks ~= 5 blocks/SM x 148 SMs, single wave
__device__ double g_part[MAXB][NBLK][NACC];
__device__ unsigned int g_count[MAXB];   // zero-initialized at module load

// 16B-padded point scratch: gathers become single-sector LDG.128 and the
// DRAM read of the clouds happens LINEARLY in the repack kernel instead of
// in random gather order (random 32B-sector DRAM ~1.7TB/s was the measured
// roofline R3..R11; the R12 prefetch-hint version recovered only part of it
// because the hint races the demand misses).
#define MAXPTS (16 * 200000)
__device__ float4 g_X4[MAXPTS];
__device__ float4 g_Y4[MAXPTS];

__global__ void __launch_bounds__(256) repack_kernel(
        const float* __restrict__ xyzs1,
        const float* __restrict__ xyzs2,
        int total3) {              // total3 = 3 * B * M floats per cloud
    float* __restrict__ xf = (float*)g_X4;
    float* __restrict__ yf = (float*)g_Y4;
    const int stride = gridDim.x * blockDim.x;
    for (int i = blockIdx.x * blockDim.x + threadIdx.x; i < total3; i += stride) {
        const int p = i / 3;           // point index
        const int c = i - 3 * p;       // component 0..2
        // linear, evict-first read of the source cloud (touched once here)
        xf[4 * p + c] = __ldcs(&xyzs1[i]);
        yf[4 * p + c] = __ldcs(&xyzs2[i]);
    }
}

__global__ void __launch_bounds__(256) procrustes_kernel(
        const float* __restrict__ xyzs1,
        const float* __restrict__ xyzs2,
        const int2* __restrict__ pairs,
        const float* __restrict__ weights,
        float* __restrict__ out,
        int M, int N, int B, int useRepack) {
    const int b = blockIdx.y;
    const int2*  __restrict__ P = pairs + (size_t)b * N;
    const float* __restrict__ W = weights + (size_t)b * N;

    float a[NACC];
#pragma unroll
    for (int k = 0; k < NACC; k++) a[k] = 0.0f;

    const int stride = gridDim.x * blockDim.x;

    if (useRepack) {
        // Gathers hit the L2-resident padded scratch: 1 LDG.128 = 1 sector.
        const float4* __restrict__ X4 = g_X4 + (size_t)b * M;
        const float4* __restrict__ Y4 = g_Y4 + (size_t)b * M;
        for (int n = blockIdx.x * blockDim.x + threadIdx.x; n < N; n += stride) {
            int2 ij = __ldcs(&P[n]);
            float w = __ldcs(&W[n]);
            float4 xv = __ldg(&X4[ij.x]);
            float4 yv = __ldg(&Y4[ij.y]);

            a[0] += fabsf(w);
            a[1] += w;
            float wx0 = w * xv.x, wx1 = w * xv.y, wx2 = w * xv.z;
            a[2] += wx0;  a[3] += wx1;  a[4] += wx2;
            a[5] += w * yv.x; a[6] += w * yv.y; a[7] += w * yv.z;
            a[8]  += yv.x * wx0; a[9]  += yv.x * wx1; a[10] += yv.x * wx2;
            a[11] += yv.y * wx0; a[12] += yv.y * wx1; a[13] += yv.y * wx2;
            a[14] += yv.z * wx0; a[15] += yv.z * wx1; a[16] += yv.z * wx2;
        }
    } else {
        // Fallback (shapes exceeding scratch): float2-pair direct gather.
        const float2* __restrict__ X2 = (const float2*)(xyzs1 + (size_t)b * M * 3);
        const float2* __restrict__ Y2 = (const float2*)(xyzs2 + (size_t)b * M * 3);
        for (int n = blockIdx.x * blockDim.x + threadIdx.x; n < N; n += stride) {
            int2 ij = __ldcs(&P[n]);
            float w = __ldcs(&W[n]);
            const int jx = (3 * ij.x) >> 1;
            const int jy = (3 * ij.y) >> 1;
            float2 xa = __ldg(&X2[jx]);
            float2 xb = __ldg(&X2[jx + 1]);
            float2 ya = __ldg(&Y2[jy]);
            float2 yb = __ldg(&Y2[jy + 1]);
            const bool ox = ij.x & 1;
            const bool oy = ij.y & 1;
            float x0 = ox ? xa.y : xa.x;
            float x1 = ox ? xb.x : xa.y;
            float x2 = ox ? xb.y : xb.x;
            float y0 = oy ? ya.y : ya.x;
            float y1 = oy ? yb.x : ya.y;
            float y2 = oy ? yb.y : yb.x;

            a[0] += fabsf(w);
            a[1] += w;
            float wx0 = w * x0, wx1 = w * x1, wx2 = w * x2;
            a[2] += wx0;  a[3] += wx1;  a[4] += wx2;
            a[5] += w * y0; a[6] += w * y1; a[7] += w * y2;
            a[8]  += y0 * wx0; a[9]  += y0 * wx1; a[10] += y0 * wx2;
            a[11] += y1 * wx0; a[12] += y1 * wx1; a[13] += y1 * wx2;
            a[14] += y2 * wx0; a[15] += y2 * wx1; a[16] += y2 * wx2;
        }
    }

    // ---- block reduce: warp shuffle -> shared float -> global partials ----
    __shared__ float part[NACC];
    if (threadIdx.x < NACC) part[threadIdx.x] = 0.0f;
    __syncthreads();

    const int lane = threadIdx.x & 31;
#pragma unroll
    for (int k = 0; k < NACC; k++) {
        float v = a[k];
#pragma unroll
        for (int off = 16; off > 0; off >>= 1)
            v += __shfl_down_sync(0xffffffffu, v, off);
        if (lane == 0) atomicAdd(&part[k], v);
    }
    __syncthreads();
    if (threadIdx.x < NACC)
        g_part[b][blockIdx.x][threadIdx.x] = (double)part[threadIdx.x];

    // ---- last block of this batch does the finalize (fused) ----
    asm volatile("fence.acq_rel.gpu;" ::: "memory");
    __shared__ bool isLast;
    if (threadIdx.x == 0) {
        unsigned int old = atomicInc(&g_count[b], NBLK - 1);
        isLast = (old == NBLK - 1);
    }
    __syncthreads();
    if (!isLast) return;
    asm volatile("fence.acq_rel.gpu;" ::: "memory");

    // Parallel cross-block reduction: 8 chunks x 17 accumulators = 136 threads.
    __shared__ double sred[8][NACC];
    __shared__ double sacc[NACC];
    {
        const int t = threadIdx.x;
        if (t < 8 * NACC) {
            const int k = t % NACC;
            const int c = t / NACC;
            double s = 0.0;
            for (int blk = c; blk < NBLK; blk += 8)
                s += g_part[b][blk][k];
            sred[c][k] = s;
        }
        __syncthreads();
        if (t < NACC) {
            double s = 0.0;
#pragma unroll
            for (int c = 0; c < 8; c++) s += sred[c][t];
            sacc[t] = s;
        }
        __syncthreads();
    }
    if (threadIdx.x != 0) return;

    double acc[NACC];
#pragma unroll
    for (int k = 0; k < NACC; k++) acc[k] = sacc[k];

    const double EPS = 1.1920928955078125e-07; // float32 eps
    double W1 = acc[0];
    double invd = 1.0 / (W1 + EPS);
    double cd   = acc[1] * invd;
    double muxd[3] = { acc[2] * invd, acc[3] * invd, acc[4] * invd };
    double muyd[3] = { acc[5] * invd, acc[6] * invd, acc[7] * invd };

    float S[3][3];
    double fd = 2.0 - cd;
#pragma unroll
    for (int i = 0; i < 3; i++)
#pragma unroll
        for (int j = 0; j < 3; j++)
            S[i][j] = (float)(acc[8 + 3 * i + j] * invd - fd * muyd[i] * muxd[j]);

    float mux[3] = { (float)muxd[0], (float)muxd[1], (float)muxd[2] };
    float muy[3] = { (float)muyd[0], (float)muyd[1], (float)muyd[2] };

    float Bm[3][3];
#pragma unroll
    for (int i = 0; i < 3; i++)
#pragma unroll
        for (int j = 0; j < 3; j++)
            Bm[i][j] = S[0][i] * S[0][j] + S[1][i] * S[1][j] + S[2][i] * S[2][j];

    float V[3][3] = {{1,0,0},{0,1,0},{0,0,1}};

#pragma unroll
    for (int sweep = 0; sweep < 4; sweep++) {
#pragma unroll
        for (int pair = 0; pair < 3; pair++) {
            const int p = (pair == 0) ? 0 : (pair == 1) ? 0 : 1;
            const int q = (pair == 0) ? 1 : (pair == 1) ? 2 : 2;
            float bpq = Bm[p][q];
            if (fabsf(bpq) < 1e-12f) continue;
            float tau = __fdividef(Bm[q][q] - Bm[p][p], 2.0f * bpq);
            float t = __fdividef(copysignf(1.0f, tau),
                                 fabsf(tau) + __fsqrt_rn(1.0f + tau * tau));
            float cs = rsqrtf(1.0f + t * t);
            float sn = t * cs;

            float bpp = Bm[p][p], bqq = Bm[q][q];
            Bm[p][p] = bpp - t * bpq;
            Bm[q][q] = bqq + t * bpq;
            Bm[p][q] = Bm[q][p] = 0.0f;
            const int r = 3 - p - q;
            float brp = Bm[r][p], brq = Bm[r][q];
            Bm[r][p] = Bm[p][r] = cs * brp - sn * brq;
            Bm[r][q] = Bm[q][r] = sn * brp + cs * brq;
#pragma unroll
            for (int i = 0; i < 3; i++) {
                float vip = V[i][p], viq = V[i][q];
                V[i][p] = cs * vip - sn * viq;
                V[i][q] = sn * vip + cs * viq;
            }
        }
    }

    float lam[3] = { Bm[0][0], Bm[1][1], Bm[2][2] };
    int idx[3] = {0, 1, 2};
#pragma unroll
    for (int i = 0; i < 2; i++)
#pragma unroll
        for (int j = 0; j < 2 - i; j++)
            if (lam[idx[j]] < lam[idx[j + 1]]) { int tt = idx[j]; idx[j] = idx[j + 1]; idx[j + 1] = tt; }

    float v1[3], v2[3], v3[3];
#pragma unroll
    for (int i = 0; i < 3; i++) {
        v1[i] = V[i][idx[0]];
        v2[i] = V[i][idx[1]];
        v3[i] = V[i][idx[2]];
    }

    float u1[3], u2[3], u3[3];
#pragma unroll
    for (int i = 0; i < 3; i++)
        u1[i] = S[i][0] * v1[0] + S[i][1] * v1[1] + S[i][2] * v1[2];
    float nn1 = u1[0]*u1[0] + u1[1]*u1[1] + u1[2]*u1[2];
    if (nn1 > 1e-30f) { float r = rsqrtf(nn1); u1[0] *= r; u1[1] *= r; u1[2] *= r; }
    else { u1[0] = 1.0f; u1[1] = 0.0f; u1[2] = 0.0f; }

#pragma unroll
    for (int i = 0; i < 3; i++)
        u2[i] = S[i][0] * v2[0] + S[i][1] * v2[1] + S[i][2] * v2[2];
    float d12 = u2[0]*u1[0] + u2[1]*u1[1] + u2[2]*u1[2];
#pragma unroll
    for (int i = 0; i < 3; i++) u2[i] -= d12 * u1[i];
    float nn2 = u2[0]*u2[0] + u2[1]*u2[1] + u2[2]*u2[2];
    if (nn2 > 1e-30f) { float r = rsqrtf(nn2); u2[0] *= r; u2[1] *= r; u2[2] *= r; }
    else {
        float ax = fabsf(u1[0]), ay = fabsf(u1[1]), az = fabsf(u1[2]);
        float e[3] = {0,0,0};
        if (ax <= ay && ax <= az) e[0] = 1.0f; else if (ay <= az) e[1] = 1.0f; else e[2] = 1.0f;
        u2[0] = u1[1]*e[2] - u1[2]*e[1];
        u2[1] = u1[2]*e[0] - u1[0]*e[2];
        u2[2] = u1[0]*e[1] - u1[1]*e[0];
        float rn = rsqrtf(u2[0]*u2[0] + u2[1]*u2[1] + u2[2]*u2[2]);
        u2[0] *= rn; u2[1] *= rn; u2[2] *= rn;
    }
    u3[0] = u1[1]*u2[2] - u1[2]*u2[1];
    u3[1] = u1[2]*u2[0] - u1[0]*u2[2];
    u3[2] = u1[0]*u2[1] - u1[1]*u2[0];

    // Parity over the SORTED column order [v1|v2|v3].
    float detVs = v1[0] * (v2[1] * v3[2] - v2[2] * v3[1])
                - v1[1] * (v2[0] * v3[2] - v2[2] * v3[0])
                + v1[2] * (v2[0] * v3[1] - v2[1] * v3[0]);
    float s3 = (detVs < 0.0f) ? -1.0f : 1.0f;

    float R[3][3];
#pragma unroll
    for (int i = 0; i < 3; i++)
#pragma unroll
        for (int j = 0; j < 3; j++)
            R[i][j] = u1[i]*v1[j] + u2[i]*v2[j] + s3 * u3[i]*v3[j];

    float tvec[3];
#pragma unroll
    for (int i = 0; i < 3; i++)
        tvec[i] = muy[i] - (R[i][0]*mux[0] + R[i][1]*mux[1] + R[i][2]*mux[2]);

    // outputs: Rs [B,3,3] | ts [B,3] | ws [B]
#pragma unroll
    for (int i = 0; i < 3; i++)
#pragma unroll
        for (int j = 0; j < 3; j++)
            out[b * 9 + i * 3 + j] = R[i][j];
#pragma unroll
    for (int i = 0; i < 3; i++)
        out[B * 9 + b * 3 + i] = tvec[i];
    out[B * 12 + b] = (float)acc[1];   // ws = sum w
}

extern "C" void kernel_launch(void* const* d_in, const int* in_sizes, int n_in,
                              void* d_out, int out_size) {
    const float* xyzs1   = (const float*)d_in[0];
    const float* xyzs2   = (const float*)d_in[1];
    const int2*  pairs   = (const int2*)d_in[2];
    const float* weights = (const float*)d_in[3];
    float* out = (float*)d_out;

    int B = out_size / 13;              // 9 + 3 + 1 floats per batch
    if (B < 1) B = 1;
    if (B > MAXB) B = MAXB;
    int M = in_sizes[0] / (3 * B);
    int N = in_sizes[3] / B;

    int useRepack = ((size_t)B * M <= (size_t)MAXPTS) ? 1 : 0;
    if (useRepack) {
        int total3 = 3 * B * M;
        repack_kernel<<<1480, 256>>>(xyzs1, xyzs2, total3);
    }

    dim3 grid(NBLK, B);
    procrustes_kernel<<<grid, 256>>>(xyzs1, xyzs2, pairs, weights, out,
                                     M, N, B, useRepack);
}

// round 14
// speedup vs baseline: 2.0974x; 2.0974x over previous
#include <cuda_runtime.h>
#include <math.h>

// 17 accumulators per batch:
// [0]=sum|w|, [1]=sum w, [2..4]=sum w*X, [5..7]=sum w*Y, [8..16]=sum w*Y_i*X_j
#define NACC 17
#define MAXB 64
#define NBLK 55    // 55 x 16 = 880 blocks ~= 6 blocks/SM x 148 SMs, single wave
__device__ double g_part[MAXB][NBLK][NACC];
__device__ unsigned int g_count[MAXB];   // zero-initialized at module load

__global__ void __launch_bounds__(256, 6) procrustes_kernel(
        const float* __restrict__ xyzs1,
        const float* __restrict__ xyzs2,
        const int2* __restrict__ pairs,
        const float* __restrict__ weights,
        float* __restrict__ out,
        int M, int N, int B) {
    const int b = blockIdx.y;
    // View each batch's cloud as float2[] (8B aligned). Point i (bytes
    // [12i,12i+12)) is covered by float2 elements j and j+1, j = (3i)>>1:
    //   i even: x=(a.x,a.y,b.x)   i odd: x=(a.y,b.x,b.y)
    const float2* __restrict__ X2 = (const float2*)(xyzs1 + (size_t)b * M * 3);
    const float2* __restrict__ Y2 = (const float2*)(xyzs2 + (size_t)b * M * 3);
    const int2*  __restrict__ P = pairs + (size_t)b * N;
    const float* __restrict__ W = weights + (size_t)b * N;

    // ---- L2 warm-up: linear prefetch of this batch's clouds (R12: -6us).
    // Structural repack (R13) regressed badly (dirty-scratch writeback);
    // hint-based warm-up is the right variant.
    {
        const char* xc = (const char*)X2;
        const char* yc = (const char*)Y2;
        const size_t bytes = (size_t)M * 12;
        const size_t nthreads = (size_t)gridDim.x * blockDim.x;
        const size_t start = ((size_t)blockIdx.x * blockDim.x + threadIdx.x) * 128;
        for (size_t off = start; off < bytes; off += nthreads * 128) {
            asm volatile("prefetch.global.L2 [%0];" :: "l"(xc + off));
            asm volatile("prefetch.global.L2 [%0];" :: "l"(yc + off));
        }
    }

    float a[NACC];
#pragma unroll
    for (int k = 0; k < NACC; k++) a[k] = 0.0f;

    const int stride = gridDim.x * blockDim.x;
    int n = blockIdx.x * blockDim.x + threadIdx.x;

    // Unroll x2, loads batched up front (keeps ~10 independent loads in
    // flight per thread; with 48 warps/SM this is what feeds the MSHRs).
    for (; n + stride < N; n += 2 * stride) {
        const int n1 = n + stride;
        int2 p0 = __ldcs(&P[n]);
        int2 p1 = __ldcs(&P[n1]);
        float w0 = __ldcs(&W[n]);
        float w1 = __ldcs(&W[n1]);
        const int jx0 = (3 * p0.x) >> 1, jy0 = (3 * p0.y) >> 1;
        const int jx1 = (3 * p1.x) >> 1, jy1 = (3 * p1.y) >> 1;
        float2 xa0 = __ldg(&X2[jx0]);
        float2 xb0 = __ldg(&X2[jx0 + 1]);
        float2 ya0 = __ldg(&Y2[jy0]);
        float2 yb0 = __ldg(&Y2[jy0 + 1]);
        float2 xa1 = __ldg(&X2[jx1]);
        float2 xb1 = __ldg(&X2[jx1 + 1]);
        float2 ya1 = __ldg(&Y2[jy1]);
        float2 yb1 = __ldg(&Y2[jy1 + 1]);

        {
            const bool ox = p0.x & 1, oy = p0.y & 1;
            float x0 = ox ? xa0.y : xa0.x;
            float x1 = ox ? xb0.x : xa0.y;
            float x2 = ox ? xb0.y : xb0.x;
            float y0 = oy ? ya0.y : ya0.x;
            float y1 = oy ? yb0.x : ya0.y;
            float y2 = oy ? yb0.y : yb0.x;
            a[0] += fabsf(w0);
            a[1] += w0;
            float wx0 = w0 * x0, wx1 = w0 * x1, wx2 = w0 * x2;
            a[2] += wx0;  a[3] += wx1;  a[4] += wx2;
            a[5] += w0 * y0; a[6] += w0 * y1; a[7] += w0 * y2;
            a[8]  += y0 * wx0; a[9]  += y0 * wx1; a[10] += y0 * wx2;
            a[11] += y1 * wx0; a[12] += y1 * wx1; a[13] += y1 * wx2;
            a[14] += y2 * wx0; a[15] += y2 * wx1; a[16] += y2 * wx2;
        }
        {
            const bool ox = p1.x & 1, oy = p1.y & 1;
            float x0 = ox ? xa1.y : xa1.x;
            float x1 = ox ? xb1.x : xa1.y;
            float x2 = ox ? xb1.y : xb1.x;
            float y0 = oy ? ya1.y : ya1.x;
            float y1 = oy ? yb1.x : ya1.y;
            float y2 = oy ? yb1.y : yb1.x;
            a[0] += fabsf(w1);
            a[1] += w1;
            float wx0 = w1 * x0, wx1 = w1 * x1, wx2 = w1 * x2;
            a[2] += wx0;  a[3] += wx1;  a[4] += wx2;
            a[5] += w1 * y0; a[6] += w1 * y1; a[7] += w1 * y2;
            a[8]  += y0 * wx0; a[9]  += y0 * wx1; a[10] += y0 * wx2;
            a[11] += y1 * wx0; a[12] += y1 * wx1; a[13] += y1 * wx2;
            a[14] += y2 * wx0; a[15] += y2 * wx1; a[16] += y2 * wx2;
        }
    }
    if (n < N) {
        int2 p0 = __ldcs(&P[n]);
        float w0 = __ldcs(&W[n]);
        const int jx0 = (3 * p0.x) >> 1, jy0 = (3 * p0.y) >> 1;
        float2 xa0 = __ldg(&X2[jx0]);
        float2 xb0 = __ldg(&X2[jx0 + 1]);
        float2 ya0 = __ldg(&Y2[jy0]);
        float2 yb0 = __ldg(&Y2[jy0 + 1]);
        const bool ox = p0.x & 1, oy = p0.y & 1;
        float x0 = ox ? xa0.y : xa0.x;
        float x1 = ox ? xb0.x : xa0.y;
        float x2 = ox ? xb0.y : xb0.x;
        float y0 = oy ? ya0.y : ya0.x;
        float y1 = oy ? yb0.x : ya0.y;
        float y2 = oy ? yb0.y : yb0.x;
        a[0] += fabsf(w0);
        a[1] += w0;
        float wx0 = w0 * x0, wx1 = w0 * x1, wx2 = w0 * x2;
        a[2] += wx0;  a[3] += wx1;  a[4] += wx2;
        a[5] += w0 * y0; a[6] += w0 * y1; a[7] += w0 * y2;
        a[8]  += y0 * wx0; a[9]  += y0 * wx1; a[10] += y0 * wx2;
        a[11] += y1 * wx0; a[12] += y1 * wx1; a[13] += y1 * wx2;
        a[14] += y2 * wx0; a[15] += y2 * wx1; a[16] += y2 * wx2;
    }

    // ---- block reduce: warp shuffle -> shared float -> global partials ----
    __shared__ float part[NACC];
    if (threadIdx.x < NACC) part[threadIdx.x] = 0.0f;
    __syncthreads();

    const int lane = threadIdx.x & 31;
#pragma unroll
    for (int k = 0; k < NACC; k++) {
        float v = a[k];
#pragma unroll
        for (int off = 16; off > 0; off >>= 1)
            v += __shfl_down_sync(0xffffffffu, v, off);
        if (lane == 0) atomicAdd(&part[k], v);
    }
    __syncthreads();
    if (threadIdx.x < NACC)
        g_part[b][blockIdx.x][threadIdx.x] = (double)part[threadIdx.x];

    // ---- last block of this batch does the finalize (fused) ----
    asm volatile("fence.acq_rel.gpu;" ::: "memory");
    __shared__ bool isLast;
    if (threadIdx.x == 0) {
        unsigned int old = atomicInc(&g_count[b], NBLK - 1);
        isLast = (old == NBLK - 1);
    }
    __syncthreads();
    if (!isLast) return;
    asm volatile("fence.acq_rel.gpu;" ::: "memory");

    // Parallel cross-block reduction: 8 chunks x 17 accumulators = 136 threads.
    __shared__ double sred[8][NACC];
    __shared__ double sacc[NACC];
    {
        const int t = threadIdx.x;
        if (t < 8 * NACC) {
            const int k = t % NACC;
            const int c = t / NACC;
            double s = 0.0;
            for (int blk = c; blk < NBLK; blk += 8)
                s += g_part[b][blk][k];
            sred[c][k] = s;
        }
        __syncthreads();
        if (t < NACC) {
            double s = 0.0;
#pragma unroll
            for (int c = 0; c < 8; c++) s += sred[c][t];
            sacc[t] = s;
        }
        __syncthreads();
    }
    if (threadIdx.x != 0) return;

    double acc[NACC];
#pragma unroll
    for (int k = 0; k < NACC; k++) acc[k] = sacc[k];

    const double EPS = 1.1920928955078125e-07; // float32 eps
    double W1 = acc[0];
    double invd = 1.0 / (W1 + EPS);
    double cd   = acc[1] * invd;
    double muxd[3] = { acc[2] * invd, acc[3] * invd, acc[4] * invd };
    double muyd[3] = { acc[5] * invd, acc[6] * invd, acc[7] * invd };

    float S[3][3];
    double fd = 2.0 - cd;
#pragma unroll
    for (int i = 0; i < 3; i++)
#pragma unroll
        for (int j = 0; j < 3; j++)
            S[i][j] = (float)(acc[8 + 3 * i + j] * invd - fd * muyd[i] * muxd[j]);

    float mux[3] = { (float)muxd[0], (float)muxd[1], (float)muxd[2] };
    float muy[3] = { (float)muyd[0], (float)muyd[1], (float)muyd[2] };

    float Bm[3][3];
#pragma unroll
    for (int i = 0; i < 3; i++)
#pragma unroll
        for (int j = 0; j < 3; j++)
            Bm[i][j] = S[0][i] * S[0][j] + S[1][i] * S[1][j] + S[2][i] * S[2][j];

    float V[3][3] = {{1,0,0},{0,1,0},{0,0,1}};

#pragma unroll
    for (int sweep = 0; sweep < 4; sweep++) {
#pragma unroll
        for (int pair = 0; pair < 3; pair++) {
            const int p = (pair == 0) ? 0 : (pair == 1) ? 0 : 1;
            const int q = (pair == 0) ? 1 : (pair == 1) ? 2 : 2;
            float bpq = Bm[p][q];
            if (fabsf(bpq) < 1e-12f) continue;
            float tau = __fdividef(Bm[q][q] - Bm[p][p], 2.0f * bpq);
            float t = __fdividef(copysignf(1.0f, tau),
                                 fabsf(tau) + __fsqrt_rn(1.0f + tau * tau));
            float cs = rsqrtf(1.0f + t * t);
            float sn = t * cs;

            float bpp = Bm[p][p], bqq = Bm[q][q];
            Bm[p][p] = bpp - t * bpq;
            Bm[q][q] = bqq + t * bpq;
            Bm[p][q] = Bm[q][p] = 0.0f;
            const int r = 3 - p - q;
            float brp = Bm[r][p], brq = Bm[r][q];
            Bm[r][p] = Bm[p][r] = cs * brp - sn * brq;
            Bm[r][q] = Bm[q][r] = sn * brp + cs * brq;
#pragma unroll
            for (int i = 0; i < 3; i++) {
                float vip = V[i][p], viq = V[i][q];
                V[i][p] = cs * vip - sn * viq;
                V[i][q] = sn * vip + cs * viq;
            }
        }
    }

    float lam[3] = { Bm[0][0], Bm[1][1], Bm[2][2] };
    int idx[3] = {0, 1, 2};
#pragma unroll
    for (int i = 0; i < 2; i++)
#pragma unroll
        for (int j = 0; j < 2 - i; j++)
            if (lam[idx[j]] < lam[idx[j + 1]]) { int tt = idx[j]; idx[j] = idx[j + 1]; idx[j + 1] = tt; }

    float v1[3], v2[3], v3[3];
#pragma unroll
    for (int i = 0; i < 3; i++) {
        v1[i] = V[i][idx[0]];
        v2[i] = V[i][idx[1]];
        v3[i] = V[i][idx[2]];
    }

    float u1[3], u2[3], u3[3];
#pragma unroll
    for (int i = 0; i < 3; i++)
        u1[i] = S[i][0] * v1[0] + S[i][1] * v1[1] + S[i][2] * v1[2];
    float nn1 = u1[0]*u1[0] + u1[1]*u1[1] + u1[2]*u1[2];
    if (nn1 > 1e-30f) { float r = rsqrtf(nn1); u1[0] *= r; u1[1] *= r; u1[2] *= r; }
    else { u1[0] = 1.0f; u1[1] = 0.0f; u1[2] = 0.0f; }

#pragma unroll
    for (int i = 0; i < 3; i++)
        u2[i] = S[i][0] * v2[0] + S[i][1] * v2[1] + S[i][2] * v2[2];
    float d12 = u2[0]*u1[0] + u2[1]*u1[1] + u2[2]*u1[2];
#pragma unroll
    for (int i = 0; i < 3; i++) u2[i] -= d12 * u1[i];
    float nn2 = u2[0]*u2[0] + u2[1]*u2[1] + u2[2]*u2[2];
    if (nn2 > 1e-30f) { float r = rsqrtf(nn2); u2[0] *= r; u2[1] *= r; u2[2] *= r; }
    else {
        float ax = fabsf(u1[0]), ay = fabsf(u1[1]), az = fabsf(u1[2]);
        float e[3] = {0,0,0};
        if (ax <= ay && ax <= az) e[0] = 1.0f; else if (ay <= az) e[1] = 1.0f; else e[2] = 1.0f;
        u2[0] = u1[1]*e[2] - u1[2]*e[1];
        u2[1] = u1[2]*e[0] - u1[0]*e[2];
        u2[2] = u1[0]*e[1] - u1[1]*e[0];
        float rn = rsqrtf(u2[0]*u2[0] + u2[1]*u2[1] + u2[2]*u2[2]);
        u2[0] *= rn; u2[1] *= rn; u2[2] *= rn;
    }
    u3[0] = u1[1]*u2[2] - u1[2]*u2[1];
    u3[1] = u1[2]*u2[0] - u1[0]*u2[2];
    u3[2] = u1[0]*u2[1] - u1[1]*u2[0];

    // Parity over the SORTED column order [v1|v2|v3].
    float detVs = v1[0] * (v2[1] * v3[2] - v2[2] * v3[1])
                - v1[1] * (v2[0] * v3[2] - v2[2] * v3[0])
                + v1[2] * (v2[0] * v3[1] - v2[1] * v3[0]);
    float s3 = (detVs < 0.0f) ? -1.0f : 1.0f;

    float R[3][3];
#pragma unroll
    for (int i = 0; i < 3; i++)
#pragma unroll
        for (int j = 0; j < 3; j++)
            R[i][j] = u1[i]*v1[j] + u2[i]*v2[j] + s3 * u3[i]*v3[j];

    float tvec[3];
#pragma unroll
    for (int i = 0; i < 3; i++)
        tvec[i] = muy[i] - (R[i][0]*mux[0] + R[i][1]*mux[1] + R[i][2]*mux[2]);

    // outputs: Rs [B,3,3] | ts [B,3] | ws [B]
#pragma unroll
    for (int i = 0; i < 3; i++)
#pragma unroll
        for (int j = 0; j < 3; j++)
            out[b * 9 + i * 3 + j] = R[i][j];
#pragma unroll
    for (int i = 0; i < 3; i++)
        out[B * 9 + b * 3 + i] = tvec[i];
    out[B * 12 + b] = (float)acc[1];   // ws = sum w
}

extern "C" void kernel_launch(void* const* d_in, const int* in_sizes, int n_in,
                              void* d_out, int out_size) {
    const float* xyzs1   = (const float*)d_in[0];
    const float* xyzs2   = (const float*)d_in[1];
    const int2*  pairs   = (const int2*)d_in[2];
    const float* weights = (const float*)d_in[3];
    float* out = (float*)d_out;

    int B = out_size / 13;              // 9 + 3 + 1 floats per batch
    if (B < 1) B = 1;
    if (B > MAXB) B = MAXB;
    int M = in_sizes[0] / (3 * B);
    int N = in_sizes[3] / B;

    dim3 grid(NBLK, B);
    procrustes_kernel<<<grid, 256>>>(xyzs1, xyzs2, pairs, weights, out, M, N, B);
}

// round 15
// speedup vs baseline: 2.1161x; 1.0089x over previous
#include <cuda_runtime.h>
#include <math.h>

// 17 accumulators per batch:
// [0]=sum|w|, [1]=sum w, [2..4]=sum w*X, [5..7]=sum w*Y, [8..16]=sum w*Y_i*X_j
#define NACC 17
#define MAXB 64
#define NBLK 55    // 55 x 16 = 880 blocks ~= 6 blocks/SM x 148 SMs, single wave
__device__ double g_part[MAXB][NBLK][NACC];
__device__ unsigned int g_count[MAXB];   // zero-initialized at module load

__global__ void __launch_bounds__(256, 6) procrustes_kernel(
        const float* __restrict__ xyzs1,
        const float* __restrict__ xyzs2,
        const int2* __restrict__ pairs,
        const float* __restrict__ weights,
        float* __restrict__ out,
        int M, int N, int B) {
    const int b = blockIdx.y;
    // View each batch's cloud as float2[] (8B aligned). Point i (bytes
    // [12i,12i+12)) is covered by float2 elements j and j+1, j = (3i)>>1:
    //   i even: x=(a.x,a.y,b.x)   i odd: x=(a.y,b.x,b.y)
    const float2* __restrict__ X2 = (const float2*)(xyzs1 + (size_t)b * M * 3);
    const float2* __restrict__ Y2 = (const float2*)(xyzs2 + (size_t)b * M * 3);
    const int2*  __restrict__ P = pairs + (size_t)b * N;
    const float* __restrict__ W = weights + (size_t)b * N;

    // ---- L2 warm-up: linear prefetch of this batch's clouds (R12: -6us).
    {
        const char* xc = (const char*)X2;
        const char* yc = (const char*)Y2;
        const size_t bytes = (size_t)M * 12;
        const size_t nthreads = (size_t)gridDim.x * blockDim.x;
        const size_t start = ((size_t)blockIdx.x * blockDim.x + threadIdx.x) * 128;
        for (size_t off = start; off < bytes; off += nthreads * 128) {
            asm volatile("prefetch.global.L2 [%0];" :: "l"(xc + off));
            asm volatile("prefetch.global.L2 [%0];" :: "l"(yc + off));
        }
    }

    float a[NACC];
#pragma unroll
    for (int k = 0; k < NACC; k++) a[k] = 0.0f;

    const int stride = gridDim.x * blockDim.x;

    // ---- 2-stage software pipeline: while iteration k's gathers +
    // accumulation run, iteration k+1's index/weight loads are in flight,
    // keeping the index-load latency off the critical chain feeding the
    // L1tex gather pipe (the measured bottleneck: ~0.8 wf/cyc of ~1.0).
    int n = blockIdx.x * blockDim.x + threadIdx.x;
    bool validA = (n < N);
    int2 pA = validA ? __ldcs(&P[n]) : make_int2(0, 0);
    float wA = validA ? __ldcs(&W[n]) : 0.0f;

    while (validA) {
        const int n2 = n + stride;
        const bool validB = (n2 < N);
        int2 pB = make_int2(0, 0);
        float wB = 0.0f;
        if (validB) {
            pB = __ldcs(&P[n2]);
            wB = __ldcs(&W[n2]);
        }

        // gathers for the current pair (indices already resident)
        const int jx = (3 * pA.x) >> 1;
        const int jy = (3 * pA.y) >> 1;
        float2 xa = __ldg(&X2[jx]);
        float2 xb = __ldg(&X2[jx + 1]);
        float2 ya = __ldg(&Y2[jy]);
        float2 yb = __ldg(&Y2[jy + 1]);
        const bool ox = pA.x & 1;
        const bool oy = pA.y & 1;
        float x0 = ox ? xa.y : xa.x;
        float x1 = ox ? xb.x : xa.y;
        float x2 = ox ? xb.y : xb.x;
        float y0 = oy ? ya.y : ya.x;
        float y1 = oy ? yb.x : ya.y;
        float y2 = oy ? yb.y : yb.x;

        a[0] += fabsf(wA);
        a[1] += wA;
        float wx0 = wA * x0, wx1 = wA * x1, wx2 = wA * x2;
        a[2] += wx0;  a[3] += wx1;  a[4] += wx2;
        a[5] += wA * y0; a[6] += wA * y1; a[7] += wA * y2;
        a[8]  += y0 * wx0; a[9]  += y0 * wx1; a[10] += y0 * wx2;
        a[11] += y1 * wx0; a[12] += y1 * wx1; a[13] += y1 * wx2;
        a[14] += y2 * wx0; a[15] += y2 * wx1; a[16] += y2 * wx2;

        n = n2;
        pA = pB;
        wA = wB;
        validA = validB;
    }

    // ---- block reduce: warp shuffle -> shared float -> global partials ----
    __shared__ float part[NACC];
    if (threadIdx.x < NACC) part[threadIdx.x] = 0.0f;
    __syncthreads();

    const int lane = threadIdx.x & 31;
#pragma unroll
    for (int k = 0; k < NACC; k++) {
        float v = a[k];
#pragma unroll
        for (int off = 16; off > 0; off >>= 1)
            v += __shfl_down_sync(0xffffffffu, v, off);
        if (lane == 0) atomicAdd(&part[k], v);
    }
    __syncthreads();
    if (threadIdx.x < NACC)
        g_part[b][blockIdx.x][threadIdx.x] = (double)part[threadIdx.x];

    // ---- last block of this batch does the finalize (fused) ----
    asm volatile("fence.acq_rel.gpu;" ::: "memory");
    __shared__ bool isLast;
    if (threadIdx.x == 0) {
        unsigned int old = atomicInc(&g_count[b], NBLK - 1);
        isLast = (old == NBLK - 1);
    }
    __syncthreads();
    if (!isLast) return;
    asm volatile("fence.acq_rel.gpu;" ::: "memory");

    // Parallel cross-block reduction: 8 chunks x 17 accumulators = 136 threads.
    __shared__ double sred[8][NACC];
    __shared__ double sacc[NACC];
    {
        const int t = threadIdx.x;
        if (t < 8 * NACC) {
            const int k = t % NACC;
            const int c = t / NACC;
            double s = 0.0;
            for (int blk = c; blk < NBLK; blk += 8)
                s += g_part[b][blk][k];
            sred[c][k] = s;
        }
        __syncthreads();
        if (t < NACC) {
            double s = 0.0;
#pragma unroll
            for (int c = 0; c < 8; c++) s += sred[c][t];
            sacc[t] = s;
        }
        __syncthreads();
    }
    if (threadIdx.x != 0) return;

    double acc[NACC];
#pragma unroll
    for (int k = 0; k < NACC; k++) acc[k] = sacc[k];

    const double EPS = 1.1920928955078125e-07; // float32 eps
    double W1 = acc[0];
    double invd = 1.0 / (W1 + EPS);
    double cd   = acc[1] * invd;
    double muxd[3] = { acc[2] * invd, acc[3] * invd, acc[4] * invd };
    double muyd[3] = { acc[5] * invd, acc[6] * invd, acc[7] * invd };

    float S[3][3];
    double fd = 2.0 - cd;
#pragma unroll
    for (int i = 0; i < 3; i++)
#pragma unroll
        for (int j = 0; j < 3; j++)
            S[i][j] = (float)(acc[8 + 3 * i + j] * invd - fd * muyd[i] * muxd[j]);

    float mux[3] = { (float)muxd[0], (float)muxd[1], (float)muxd[2] };
    float muy[3] = { (float)muyd[0], (float)muyd[1], (float)muyd[2] };

    float Bm[3][3];
#pragma unroll
    for (int i = 0; i < 3; i++)
#pragma unroll
        for (int j = 0; j < 3; j++)
            Bm[i][j] = S[0][i] * S[0][j] + S[1][i] * S[1][j] + S[2][i] * S[2][j];

    float V[3][3] = {{1,0,0},{0,1,0},{0,0,1}};

#pragma unroll
    for (int sweep = 0; sweep < 4; sweep++) {
#pragma unroll
        for (int pair = 0; pair < 3; pair++) {
            const int p = (pair == 0) ? 0 : (pair == 1) ? 0 : 1;
            const int q = (pair == 0) ? 1 : (pair == 1) ? 2 : 2;
            float bpq = Bm[p][q];
            if (fabsf(bpq) < 1e-12f) continue;
            float tau = __fdividef(Bm[q][q] - Bm[p][p], 2.0f * bpq);
            float t = __fdividef(copysignf(1.0f, tau),
                                 fabsf(tau) + __fsqrt_rn(1.0f + tau * tau));
            float cs = rsqrtf(1.0f + t * t);
            float sn = t * cs;

            float bpp = Bm[p][p], bqq = Bm[q][q];
            Bm[p][p] = bpp - t * bpq;
            Bm[q][q] = bqq + t * bpq;
            Bm[p][q] = Bm[q][p] = 0.0f;
            const int r = 3 - p - q;
            float brp = Bm[r][p], brq = Bm[r][q];
            Bm[r][p] = Bm[p][r] = cs * brp - sn * brq;
            Bm[r][q] = Bm[q][r] = sn * brp + cs * brq;
#pragma unroll
            for (int i = 0; i < 3; i++) {
                float vip = V[i][p], viq = V[i][q];
                V[i][p] = cs * vip - sn * viq;
                V[i][q] = sn * vip + cs * viq;
            }
        }
    }

    float lam[3] = { Bm[0][0], Bm[1][1], Bm[2][2] };
    int idx[3] = {0, 1, 2};
#pragma unroll
    for (int i = 0; i < 2; i++)
#pragma unroll
        for (int j = 0; j < 2 - i; j++)
            if (lam[idx[j]] < lam[idx[j + 1]]) { int tt = idx[j]; idx[j] = idx[j + 1]; idx[j + 1] = tt; }

    float v1[3], v2[3], v3[3];
#pragma unroll
    for (int i = 0; i < 3; i++) {
        v1[i] = V[i][idx[0]];
        v2[i] = V[i][idx[1]];
        v3[i] = V[i][idx[2]];
    }

    float u1[3], u2[3], u3[3];
#pragma unroll
    for (int i = 0; i < 3; i++)
        u1[i] = S[i][0] * v1[0] + S[i][1] * v1[1] + S[i][2] * v1[2];
    float nn1 = u1[0]*u1[0] + u1[1]*u1[1] + u1[2]*u1[2];
    if (nn1 > 1e-30f) { float r = rsqrtf(nn1); u1[0] *= r; u1[1] *= r; u1[2] *= r; }
    else { u1[0] = 1.0f; u1[1] = 0.0f; u1[2] = 0.0f; }

#pragma unroll
    for (int i = 0; i < 3; i++)
        u2[i] = S[i][0] * v2[0] + S[i][1] * v2[1] + S[i][2] * v2[2];
    float d12 = u2[0]*u1[0] + u2[1]*u1[1] + u2[2]*u1[2];
#pragma unroll
    for (int i = 0; i < 3; i++) u2[i] -= d12 * u1[i];
    float nn2 = u2[0]*u2[0] + u2[1]*u2[1] + u2[2]*u2[2];
    if (nn2 > 1e-30f) { float r = rsqrtf(nn2); u2[0] *= r; u2[1] *= r; u2[2] *= r; }
    else {
        float ax = fabsf(u1[0]), ay = fabsf(u1[1]), az = fabsf(u1[2]);
        float e[3] = {0,0,0};
        if (ax <= ay && ax <= az) e[0] = 1.0f; else if (ay <= az) e[1] = 1.0f; else e[2] = 1.0f;
        u2[0] = u1[1]*e[2] - u1[2]*e[1];
        u2[1] = u1[2]*e[0] - u1[0]*e[2];
        u2[2] = u1[0]*e[1] - u1[1]*e[0];
        float rn = rsqrtf(u2[0]*u2[0] + u2[1]*u2[1] + u2[2]*u2[2]);
        u2[0] *= rn; u2[1] *= rn; u2[2] *= rn;
    }
    u3[0] = u1[1]*u2[2] - u1[2]*u2[1];
    u3[1] = u1[2]*u2[0] - u1[0]*u2[2];
    u3[2] = u1[0]*u2[1] - u1[1]*u2[0];

    // Parity over the SORTED column order [v1|v2|v3].
    float detVs = v1[0] * (v2[1] * v3[2] - v2[2] * v3[1])
                - v1[1] * (v2[0] * v3[2] - v2[2] * v3[0])
                + v1[2] * (v2[0] * v3[1] - v2[1] * v3[0]);
    float s3 = (detVs < 0.0f) ? -1.0f : 1.0f;

    float R[3][3];
#pragma unroll
    for (int i = 0; i < 3; i++)
#pragma unroll
        for (int j = 0; j < 3; j++)
            R[i][j] = u1[i]*v1[j] + u2[i]*v2[j] + s3 * u3[i]*v3[j];

    float tvec[3];
#pragma unroll
    for (int i = 0; i < 3; i++)
        tvec[i] = muy[i] - (R[i][0]*mux[0] + R[i][1]*mux[1] + R[i][2]*mux[2]);

    // outputs: Rs [B,3,3] | ts [B,3] | ws [B]
#pragma unroll
    for (int i = 0; i < 3; i++)
#pragma unroll
        for (int j = 0; j < 3; j++)
            out[b * 9 + i * 3 + j] = R[i][j];
#pragma unroll
    for (int i = 0; i < 3; i++)
        out[B * 9 + b * 3 + i] = tvec[i];
    out[B * 12 + b] = (float)acc[1];   // ws = sum w
}

extern "C" void kernel_launch(void* const* d_in, const int* in_sizes, int n_in,
                              void* d_out, int out_size) {
    const float* xyzs1   = (const float*)d_in[0];
    const float* xyzs2   = (const float*)d_in[1];
    const int2*  pairs   = (const int2*)d_in[2];
    const float* weights = (const float*)d_in[3];
    float* out = (float*)d_out;

    int B = out_size / 13;              // 9 + 3 + 1 floats per batch
    if (B < 1) B = 1;
    if (B > MAXB) B = MAXB;
    int M = in_sizes[0] / (3 * B);
    int N = in_sizes[3] / B;

    dim3 grid(NBLK, B);
    procrustes_kernel<<<grid, 256>>>(xyzs1, xyzs2, pairs, weights, out, M, N, B);
}

// round 16
// speedup vs baseline: 2.5169x; 1.1894x over previous
#include <cuda_runtime.h>
#include <math.h>

// 17 accumulators per batch:
// [0]=sum|w|, [1]=sum w, [2..4]=sum w*X, [5..7]=sum w*Y, [8..16]=sum w*Y_i*X_j
#define NACC 17
#define MAXB 64
#define NBLK 46    // 46 x 16 = 736 blocks ~= 5 blocks/SM x 148 SMs, single wave
__device__ double g_part[MAXB][NBLK][NACC];
__device__ unsigned int g_count[MAXB];   // zero-initialized at module load

__global__ void __launch_bounds__(256, 5) procrustes_kernel(
        const float* __restrict__ xyzs1,
        const float* __restrict__ xyzs2,
        const int2* __restrict__ pairs,
        const float* __restrict__ weights,
        float* __restrict__ out,
        int M, int N, int B) {
    const int b = blockIdx.y;
    // View each batch's cloud as float2[] (8B aligned). Point i (bytes
    // [12i,12i+12)) is covered by float2 elements j and j+1, j = (3i)>>1:
    //   i even: x=(a.x,a.y,b.x)   i odd: x=(a.y,b.x,b.y)
    const float2* __restrict__ X2 = (const float2*)(xyzs1 + (size_t)b * M * 3);
    const float2* __restrict__ Y2 = (const float2*)(xyzs2 + (size_t)b * M * 3);
    const int2*  __restrict__ P = pairs + (size_t)b * N;
    const float* __restrict__ W = weights + (size_t)b * N;

    // ---- L2 warm-up: linear prefetch of this batch's clouds (R12: -6us).
    {
        const char* xc = (const char*)X2;
        const char* yc = (const char*)Y2;
        const size_t bytes = (size_t)M * 12;
        const size_t nthreads = (size_t)gridDim.x * blockDim.x;
        const size_t start = ((size_t)blockIdx.x * blockDim.x + threadIdx.x) * 128;
        for (size_t off = start; off < bytes; off += nthreads * 128) {
            asm volatile("prefetch.global.L2 [%0];" :: "l"(xc + off));
            asm volatile("prefetch.global.L2 [%0];" :: "l"(yc + off));
        }
    }

    float a[NACC];
#pragma unroll
    for (int k = 0; k < NACC; k++) a[k] = 0.0f;

    const int stride = gridDim.x * blockDim.x;

    // ---- Full 3-stage software pipeline --------------------------------
    // stage A (oldest): accumulate on gathers issued last iteration
    // stage B: gathers for the next pair are in flight
    // stage C: index/weight loads for the pair after that are in flight
    // This keeps the L1tex gather pipe fed continuously instead of stalling
    // each iteration's gather burst behind the previous accumulate chain.
    int n = blockIdx.x * blockDim.x + threadIdx.x;
    bool validA = (n < N);
    int2 pA = validA ? __ldcs(&P[n]) : make_int2(0, 0);
    float wA = validA ? __ldcs(&W[n]) : 0.0f;
    // issue gathers for the first pair
    float2 xaA = make_float2(0.f, 0.f), xbA = xaA, yaA = xaA, ybA = xaA;
    if (validA) {
        const int jx = (3 * pA.x) >> 1;
        const int jy = (3 * pA.y) >> 1;
        xaA = __ldg(&X2[jx]);
        xbA = __ldg(&X2[jx + 1]);
        yaA = __ldg(&Y2[jy]);
        ybA = __ldg(&Y2[jy + 1]);
    }

    while (validA) {
        // stage C: next indices
        const int n2 = n + stride;
        const bool validB = (n2 < N);
        int2 pB = make_int2(0, 0);
        float wB = 0.0f;
        if (validB) {
            pB = __ldcs(&P[n2]);
            wB = __ldcs(&W[n2]);
        }
        // stage B: next gathers (indices from previous stage C)
        float2 xaB = make_float2(0.f, 0.f), xbB = xaB, yaB = xaB, ybB = xaB;
        if (validB) {
            const int jx = (3 * pB.x) >> 1;
            const int jy = (3 * pB.y) >> 1;
            xaB = __ldg(&X2[jx]);
            xbB = __ldg(&X2[jx + 1]);
            yaB = __ldg(&Y2[jy]);
            ybB = __ldg(&Y2[jy + 1]);
        }

        // stage A: accumulate current pair (gathers issued last iteration)
        {
            const bool ox = pA.x & 1;
            const bool oy = pA.y & 1;
            float x0 = ox ? xaA.y : xaA.x;
            float x1 = ox ? xbA.x : xaA.y;
            float x2 = ox ? xbA.y : xbA.x;
            float y0 = oy ? yaA.y : yaA.x;
            float y1 = oy ? ybA.x : yaA.y;
            float y2 = oy ? ybA.y : ybA.x;

            a[0] += fabsf(wA);
            a[1] += wA;
            float wx0 = wA * x0, wx1 = wA * x1, wx2 = wA * x2;
            a[2] += wx0;  a[3] += wx1;  a[4] += wx2;
            a[5] += wA * y0; a[6] += wA * y1; a[7] += wA * y2;
            a[8]  += y0 * wx0; a[9]  += y0 * wx1; a[10] += y0 * wx2;
            a[11] += y1 * wx0; a[12] += y1 * wx1; a[13] += y1 * wx2;
            a[14] += y2 * wx0; a[15] += y2 * wx1; a[16] += y2 * wx2;
        }

        // rotate pipeline
        n = n2;
        pA = pB;  wA = wB;
        xaA = xaB; xbA = xbB; yaA = yaB; ybA = ybB;
        validA = validB;
    }

    // ---- block reduce: warp shuffle -> shared float -> global partials ----
    __shared__ float part[NACC];
    if (threadIdx.x < NACC) part[threadIdx.x] = 0.0f;
    __syncthreads();

    const int lane = threadIdx.x & 31;
#pragma unroll
    for (int k = 0; k < NACC; k++) {
        float v = a[k];
#pragma unroll
        for (int off = 16; off > 0; off >>= 1)
            v += __shfl_down_sync(0xffffffffu, v, off);
        if (lane == 0) atomicAdd(&part[k], v);
    }
    __syncthreads();
    if (threadIdx.x < NACC)
        g_part[b][blockIdx.x][threadIdx.x] = (double)part[threadIdx.x];

    // ---- last block of this batch does the finalize (fused) ----
    asm volatile("fence.acq_rel.gpu;" ::: "memory");
    __shared__ bool isLast;
    if (threadIdx.x == 0) {
        unsigned int old = atomicInc(&g_count[b], NBLK - 1);
        isLast = (old == NBLK - 1);
    }
    __syncthreads();
    if (!isLast) return;
    asm volatile("fence.acq_rel.gpu;" ::: "memory");

    // Parallel cross-block reduction: 8 chunks x 17 accumulators = 136 threads.
    __shared__ double sred[8][NACC];
    __shared__ double sacc[NACC];
    {
        const int t = threadIdx.x;
        if (t < 8 * NACC) {
            const int k = t % NACC;
            const int c = t / NACC;
            double s = 0.0;
            for (int blk = c; blk < NBLK; blk += 8)
                s += g_part[b][blk][k];
            sred[c][k] = s;
        }
        __syncthreads();
        if (t < NACC) {
            double s = 0.0;
#pragma unroll
            for (int c = 0; c < 8; c++) s += sred[c][t];
            sacc[t] = s;
        }
        __syncthreads();
    }
    if (threadIdx.x != 0) return;

    double acc[NACC];
#pragma unroll
    for (int k = 0; k < NACC; k++) acc[k] = sacc[k];

    const double EPS = 1.1920928955078125e-07; // float32 eps
    double W1 = acc[0];
    double invd = 1.0 / (W1 + EPS);
    double cd   = acc[1] * invd;
    double muxd[3] = { acc[2] * invd, acc[3] * invd, acc[4] * invd };
    double muyd[3] = { acc[5] * invd, acc[6] * invd, acc[7] * invd };

    float S[3][3];
    double fd = 2.0 - cd;
#pragma unroll
    for (int i = 0; i < 3; i++)
#pragma unroll
        for (int j = 0; j < 3; j++)
            S[i][j] = (float)(acc[8 + 3 * i + j] * invd - fd * muyd[i] * muxd[j]);

    float mux[3] = { (float)muxd[0], (float)muxd[1], (float)muxd[2] };
    float muy[3] = { (float)muyd[0], (float)muyd[1], (float)muyd[2] };

    float Bm[3][3];
#pragma unroll
    for (int i = 0; i < 3; i++)
#pragma unroll
        for (int j = 0; j < 3; j++)
            Bm[i][j] = S[0][i] * S[0][j] + S[1][i] * S[1][j] + S[2][i] * S[2][j];

    float V[3][3] = {{1,0,0},{0,1,0},{0,0,1}};

#pragma unroll
    for (int sweep = 0; sweep < 4; sweep++) {
#pragma unroll
        for (int pair = 0; pair < 3; pair++) {
            const int p = (pair == 0) ? 0 : (pair == 1) ? 0 : 1;
            const int q = (pair == 0) ? 1 : (pair == 1) ? 2 : 2;
            float bpq = Bm[p][q];
            if (fabsf(bpq) < 1e-12f) continue;
            float tau = __fdividef(Bm[q][q] - Bm[p][p], 2.0f * bpq);
            float t = __fdividef(copysignf(1.0f, tau),
                                 fabsf(tau) + __fsqrt_rn(1.0f + tau * tau));
            float cs = rsqrtf(1.0f + t * t);
            float sn = t * cs;

            float bpp = Bm[p][p], bqq = Bm[q][q];
            Bm[p][p] = bpp - t * bpq;
            Bm[q][q] = bqq + t * bpq;
            Bm[p][q] = Bm[q][p] = 0.0f;
            const int r = 3 - p - q;
            float brp = Bm[r][p], brq = Bm[r][q];
            Bm[r][p] = Bm[p][r] = cs * brp - sn * brq;
            Bm[r][q] = Bm[q][r] = sn * brp + cs * brq;
#pragma unroll
            for (int i = 0; i < 3; i++) {
                float vip = V[i][p], viq = V[i][q];
                V[i][p] = cs * vip - sn * viq;
                V[i][q] = sn * vip + cs * viq;
            }
        }
    }

    float lam[3] = { Bm[0][0], Bm[1][1], Bm[2][2] };
    int idx[3] = {0, 1, 2};
#pragma unroll
    for (int i = 0; i < 2; i++)
#pragma unroll
        for (int j = 0; j < 2 - i; j++)
            if (lam[idx[j]] < lam[idx[j + 1]]) { int tt = idx[j]; idx[j] = idx[j + 1]; idx[j + 1] = tt; }

    float v1[3], v2[3], v3[3];
#pragma unroll
    for (int i = 0; i < 3; i++) {
        v1[i] = V[i][idx[0]];
        v2[i] = V[i][idx[1]];
        v3[i] = V[i][idx[2]];
    }

    float u1[3], u2[3], u3[3];
#pragma unroll
    for (int i = 0; i < 3; i++)
        u1[i] = S[i][0] * v1[0] + S[i][1] * v1[1] + S[i][2] * v1[2];
    float nn1 = u1[0]*u1[0] + u1[1]*u1[1] + u1[2]*u1[2];
    if (nn1 > 1e-30f) { float r = rsqrtf(nn1); u1[0] *= r; u1[1] *= r; u1[2] *= r; }
    else { u1[0] = 1.0f; u1[1] = 0.0f; u1[2] = 0.0f; }

#pragma unroll
    for (int i = 0; i < 3; i++)
        u2[i] = S[i][0] * v2[0] + S[i][1] * v2[1] + S[i][2] * v2[2];
    float d12 = u2[0]*u1[0] + u2[1]*u1[1] + u2[2]*u1[2];
#pragma unroll
    for (int i = 0; i < 3; i++) u2[i] -= d12 * u1[i];
    float nn2 = u2[0]*u2[0] + u2[1]*u2[1] + u2[2]*u2[2];
    if (nn2 > 1e-30f) { float r = rsqrtf(nn2); u2[0] *= r; u2[1] *= r; u2[2] *= r; }
    else {
        float ax = fabsf(u1[0]), ay = fabsf(u1[1]), az = fabsf(u1[2]);
        float e[3] = {0,0,0};
        if (ax <= ay && ax <= az) e[0] = 1.0f; else if (ay <= az) e[1] = 1.0f; else e[2] = 1.0f;
        u2[0] = u1[1]*e[2] - u1[2]*e[1];
        u2[1] = u1[2]*e[0] - u1[0]*e[2];
        u2[2] = u1[0]*e[1] - u1[1]*e[0];
        float rn = rsqrtf(u2[0]*u2[0] + u2[1]*u2[1] + u2[2]*u2[2]);
        u2[0] *= rn; u2[1] *= rn; u2[2] *= rn;
    }
    u3[0] = u1[1]*u2[2] - u1[2]*u2[1];
    u3[1] = u1[2]*u2[0] - u1[0]*u2[2];
    u3[2] = u1[0]*u2[1] - u1[1]*u2[0];

    // Parity over the SORTED column order [v1|v2|v3].
    float detVs = v1[0] * (v2[1] * v3[2] - v2[2] * v3[1])
                - v1[1] * (v2[0] * v3[2] - v2[2] * v3[0])
                + v1[2] * (v2[0] * v3[1] - v2[1] * v3[0]);
    float s3 = (detVs < 0.0f) ? -1.0f : 1.0f;

    float R[3][3];
#pragma unroll
    for (int i = 0; i < 3; i++)
#pragma unroll
        for (int j = 0; j < 3; j++)
            R[i][j] = u1[i]*v1[j] + u2[i]*v2[j] + s3 * u3[i]*v3[j];

    float tvec[3];
#pragma unroll
    for (int i = 0; i < 3; i++)
        tvec[i] = muy[i] - (R[i][0]*mux[0] + R[i][1]*mux[1] + R[i][2]*mux[2]);

    // outputs: Rs [B,3,3] | ts [B,3] | ws [B]
#pragma unroll
    for (int i = 0; i < 3; i++)
#pragma unroll
        for (int j = 0; j < 3; j++)
            out[b * 9 + i * 3 + j] = R[i][j];
#pragma unroll
    for (int i = 0; i < 3; i++)
        out[B * 9 + b * 3 + i] = tvec[i];
    out[B * 12 + b] = (float)acc[1];   // ws = sum w
}

extern "C" void kernel_launch(void* const* d_in, const int* in_sizes, int n_in,
                              void* d_out, int out_size) {
    const float* xyzs1   = (const float*)d_in[0];
    const float* xyzs2   = (const float*)d_in[1];
    const int2*  pairs   = (const int2*)d_in[2];
    const float* weights = (const float*)d_in[3];
    float* out = (float*)d_out;

    int B = out_size / 13;              // 9 + 3 + 1 floats per batch
    if (B < 1) B = 1;
    if (B > MAXB) B = MAXB;
    int M = in_sizes[0] / (3 * B);
    int N = in_sizes[3] / B;

    dim3 grid(NBLK, B);
    procrustes_kernel<<<grid, 256>>>(xyzs1, xyzs2, pairs, weights, out, M, N, B);
}